// round 16
// baseline (speedup 1.0000x reference)
#include <cuda_runtime.h>
#include <math.h>
#include <stdint.h>

// ---------------- problem constants ----------------
#define B_WIN   4096
#define NTOK    64
#define CDIM    512
#define NHEAD   16
#define HDIM    32
#define MTOT    (B_WIN * NTOK)      // 262144 rows
#define QKV_N   1536
#define NUM_WIN 256

// padded smem row strides (floats) — multiples of 4 for float4 access
#define QPAD 36     // 144 bytes
#define SSP  68     // 272 bytes

// ---------------- scratch (static device globals; no allocation) ----------------
__device__ float g_qkv[402653184];            // [MTOT, 1536]
__device__ float g_attn[134217728];           // [MTOT, 512]  (tf32-rounded attn out)
__device__ float g_xcvt[134217728];           // [MTOT, 512]  (tf32-rounded x)
__device__ float g_wqkv[QKV_N * CDIM];        // tf32-rounded qkv_w
__device__ float g_wproj[CDIM * CDIM];        // tf32-rounded proj_w
__device__ float g_bias[NHEAD * NTOK * NTOK]; // [16,64,64]
__device__ float g_qkvbias[QKV_N];

// ---------------- helpers ----------------
__device__ __forceinline__ uint32_t f2tf32(float f) {
    uint32_t u;
    asm("cvt.rna.tf32.f32 %0, %1;" : "=r"(u) : "f"(f));
    return u;
}

__device__ __forceinline__ void mma_tf32(float* c, const uint32_t* a, const uint32_t* b) {
    asm volatile(
        "mma.sync.aligned.m16n8k8.row.col.f32.tf32.tf32.f32 "
        "{%0,%1,%2,%3}, {%4,%5,%6,%7}, {%8,%9}, {%0,%1,%2,%3};"
        : "+f"(c[0]), "+f"(c[1]), "+f"(c[2]), "+f"(c[3])
        : "r"(a[0]), "r"(a[1]), "r"(a[2]), "r"(a[3]), "r"(b[0]), "r"(b[1]));
}

__device__ __forceinline__ void ldsm_x4(uint32_t* r, uint32_t saddr) {
    asm volatile("ldmatrix.sync.aligned.m8n8.x4.shared.b16 {%0,%1,%2,%3}, [%4];"
        : "=r"(r[0]), "=r"(r[1]), "=r"(r[2]), "=r"(r[3]) : "r"(saddr));
}

__device__ __forceinline__ void cp16(void* smem, const void* g) {
    uint32_t s = (uint32_t)__cvta_generic_to_shared(smem);
    asm volatile("cp.async.cg.shared.global [%0], [%1], 16;" :: "r"(s), "l"(g));
}

// ---------------- tiny setup kernels ----------------
__global__ void qkvbias_kernel(const float* __restrict__ q_bias,
                               const float* __restrict__ v_bias,
                               float* __restrict__ out) {
    int i = blockIdx.x * blockDim.x + threadIdx.x;
    if (i >= QKV_N) return;
    float v;
    if (i < 512)       v = q_bias[i];
    else if (i < 1024) v = 0.0f;
    else               v = v_bias[i - 1024];
    out[i] = v;
}

// combined tf32 rounding pass: x -> xcvt, qkv_w -> wqkv, proj_w -> wproj
#define X4   (MTOT * CDIM / 4)        // 33554432
#define W1_4 (QKV_N * CDIM / 4)       // 196608
#define W2_4 (CDIM * CDIM / 4)        // 65536
__global__ void cvt_all_kernel(const float* __restrict__ x,
                               const float* __restrict__ w1,
                               const float* __restrict__ w2,
                               float* __restrict__ xo,
                               float* __restrict__ w1o,
                               float* __restrict__ w2o) {
    long long i = (long long)blockIdx.x * blockDim.x + threadIdx.x;
    const float4* in;
    float4* out;
    long long idx;
    if (i < X4)                    { in = (const float4*)x;  out = (float4*)xo;  idx = i; }
    else if (i < X4 + W1_4)        { in = (const float4*)w1; out = (float4*)w1o; idx = i - X4; }
    else if (i < X4 + W1_4 + W2_4) { in = (const float4*)w2; out = (float4*)w2o; idx = i - X4 - W1_4; }
    else return;
    float4 v = in[idx];
    float4 o;
    o.x = __uint_as_float(f2tf32(v.x));
    o.y = __uint_as_float(f2tf32(v.y));
    o.z = __uint_as_float(f2tf32(v.z));
    o.w = __uint_as_float(f2tf32(v.w));
    out[idx] = o;
}

__device__ __forceinline__ float cpb_coord(int x) {
    float t = (float)x * (8.0f / 7.0f);
    float m = log2f(fabsf(t) + 1.0f) * (1.0f / 3.0f);
    return (t > 0.0f) ? m : ((t < 0.0f) ? -m : 0.0f);
}

__global__ void cpb_bias_kernel(const float* __restrict__ w1,
                                const float* __restrict__ b1,
                                const float* __restrict__ w2,
                                float* __restrict__ bias_out) {
    __shared__ float tableh[225];
    int h = blockIdx.x;
    int tid = threadIdx.x;
    for (int tt = tid; tt < 225; tt += blockDim.x) {
        int ih = tt / 15, iw = tt % 15;
        float t0 = cpb_coord(ih - 7);
        float t1 = cpb_coord(iw - 7);
        float val = 0.0f;
        for (int j = 0; j < 512; j++) {
            float hj = w1[2 * j] * t0 + w1[2 * j + 1] * t1 + b1[j];
            hj = fmaxf(hj, 0.0f);
            val += hj * w2[h * 512 + j];
        }
        tableh[tt] = 16.0f / (1.0f + expf(-val));
    }
    __syncthreads();
    for (int e = tid; e < NTOK * NTOK; e += blockDim.x) {
        int i = e >> 6, j = e & 63;
        int dh = (i >> 3) - (j >> 3) + 7;
        int dw = (i & 7) - (j & 7) + 7;
        bias_out[h * 4096 + e] = tableh[dh * 15 + dw];
    }
}

// ---------------- tf32 mma.sync GEMM: 128x256 tile, 512 threads, 6-stage ring ----------------
// C[M,N] = A[M,K] @ B[N,K]^T + bias[N]
// 16 warps (2 m x 8 n), 64x32 warp tiles, BK=16, wait_group 4 (5 stages in flight).
// All operands pre-rounded tf32.

#define BM 128
#define BN 256
#define BK 16
#define NSTAGE 6
#define SPAD 20                            // 16 floats + 4 pad
#define TSZ_A (128 * SPAD)                 // 2560 floats
#define TSZ_B (256 * SPAD)                 // 5120 floats
#define STAGE_F (TSZ_A + TSZ_B)            // 7680 floats = 30720 B
#define GEMM_SMEM_BYTES (NSTAGE * STAGE_F * 4)   // 184320

__global__ __launch_bounds__(512)
void mma_gemm_bias(const float* __restrict__ A,
                   const float* __restrict__ B,
                   const float* __restrict__ bias,
                   float* __restrict__ C,
                   int M, int N, int K)
{
    extern __shared__ float sm[];
    const uint32_t sm_u32 = (uint32_t)__cvta_generic_to_shared(sm);

    const int tid  = threadIdx.x;
    const int wid  = tid >> 5;
    const int lane = tid & 31;
    const int g    = lane >> 2;
    const int t    = lane & 3;

    const int wm = (wid >> 3) * 64;       // 0 or 64
    const int wn = (wid & 7) * 32;        // 0..224

    const int bm = blockIdx.y * BM;
    const int bn = blockIdx.x * BN;

    // loader coords: A 128 rows x 4 chunks -> 1 cp16/thread
    const int laRow = tid >> 2;           // 0..127
    const int laC   = (tid & 3) * 4;      // 0,4,8,12
    // B 256 rows x 4 chunks -> 2 cp16/thread
    const int lbRow = tid >> 1;           // 0..255
    const int lbC   = (tid & 1) * 8;      // 0 or 8

    const float* Abase = A + (size_t)bm * K;
    const float* Bbase = B + (size_t)bn * K;

    const int arow = lane & 15;
    const int acol = (lane >> 4) * 4;
    const int brow = ((lane >> 4) << 3) + (lane & 7);
    const int bcol = ((lane >> 3) & 1) * 4;

    const uint32_t a_off = (uint32_t)(((wm + arow) * SPAD + acol) * 4);
    const uint32_t b_off = (uint32_t)(((wn + brow) * SPAD + bcol) * 4);

    float acc[4][4][4];
#pragma unroll
    for (int i = 0; i < 4; i++)
#pragma unroll
        for (int j = 0; j < 4; j++)
#pragma unroll
            for (int r = 0; r < 4; r++) acc[i][j][r] = 0.0f;

    const int NIT = K / BK;   // 32

    auto issue = [&](int s, int k0) {
        float* As = sm + s * STAGE_F;
        float* Bs = sm + s * STAGE_F + TSZ_A;
        cp16(&As[laRow * SPAD + laC], &Abase[(size_t)laRow * K + k0 + laC]);
        cp16(&Bs[lbRow * SPAD + lbC],     &Bbase[(size_t)lbRow * K + k0 + lbC]);
        cp16(&Bs[lbRow * SPAD + lbC + 4], &Bbase[(size_t)lbRow * K + k0 + lbC + 4]);
    };

    // prologue: fill NSTAGE-1 = 5 stages
#pragma unroll
    for (int s = 0; s < NSTAGE - 1; s++) {
        if (s < NIT) issue(s, s * BK);
        asm volatile("cp.async.commit_group;");
    }

    int slot = 0;                 // consume slot (mod NSTAGE)
    int fslot = NSTAGE - 1;       // fill slot

    for (int it = 0; it < NIT; it++) {
        asm volatile("cp.async.wait_group %0;" :: "n"(NSTAGE - 2));
        __syncthreads();

        {
            int nf = it + NSTAGE - 1;
            if (nf < NIT) issue(fslot, nf * BK);
            asm volatile("cp.async.commit_group;");
            if (++fslot == NSTAGE) fslot = 0;
        }

        const uint32_t st_base = sm_u32 + slot * (STAGE_F * 4);
        if (++slot == NSTAGE) slot = 0;
        const uint32_t a_base = st_base + a_off;
        const uint32_t b_base = st_base + (TSZ_A * 4) + b_off;

#pragma unroll
        for (int ks = 0; ks < BK; ks += 8) {
            uint32_t af[4][4];
#pragma unroll
            for (int mf = 0; mf < 4; mf++)
                ldsm_x4(af[mf], a_base + (uint32_t)((mf * 16 * SPAD + ks) * 4));

            uint32_t bf[2][4];
#pragma unroll
            for (int np = 0; np < 2; np++)
                ldsm_x4(bf[np], b_base + (uint32_t)((np * 16 * SPAD + ks) * 4));

#pragma unroll
            for (int mf = 0; mf < 4; mf++) {
#pragma unroll
                for (int np = 0; np < 2; np++) {
                    mma_tf32(acc[mf][2 * np],     af[mf], &bf[np][0]);
                    mma_tf32(acc[mf][2 * np + 1], af[mf], &bf[np][2]);
                }
            }
        }
    }

    // epilogue: add bias, store
#pragma unroll
    for (int mf = 0; mf < 4; mf++) {
#pragma unroll
        for (int nf = 0; nf < 4; nf++) {
            int row0 = bm + wm + mf * 16 + g;
            int col  = bn + wn + nf * 8 + 2 * t;
            float b0 = bias[col], b1 = bias[col + 1];
            float2 o0 = {acc[mf][nf][0] + b0, acc[mf][nf][1] + b1};
            float2 o1 = {acc[mf][nf][2] + b0, acc[mf][nf][3] + b1};
            *(float2*)&C[(size_t)row0 * N + col]       = o0;
            *(float2*)&C[(size_t)(row0 + 8) * N + col] = o1;
        }
    }
}

// ---------------- fused cosine attention per (window, head) ----------------
// 256 threads. Register-blocked S (4x4), O-phase 2-row blocking, warp softmax.
// (R14/R15-exact — measured best)
__global__ __launch_bounds__(256)
void attn_kernel(const float* __restrict__ qkv,
                 const float* __restrict__ mask,
                 const float* __restrict__ logit_scale,
                 const float* __restrict__ bias,
                 float* __restrict__ out)
{
    __shared__ float qs[NTOK][QPAD];
    __shared__ float ks[NTOK][QPAD];
    __shared__ float vs[NTOK][QPAD];
    __shared__ float S[NTOK][SSP];

    const int w = blockIdx.x;
    const int h = blockIdx.y;
    const int tid = threadIdx.x;

    const float* base = qkv + (size_t)w * NTOK * QKV_N + h * HDIM;

    for (int idx = tid; idx < NTOK * HDIM / 4; idx += 256) {
        int n = idx >> 3;
        int d = (idx & 7) * 4;
        const float* r = base + n * QKV_N + d;
        float4 q4 = *(const float4*)(r);
        float4 k4 = *(const float4*)(r + 512);
        float4 v4 = *(const float4*)(r + 1024);
        *(float4*)&qs[n][d] = q4;
        *(float4*)&ks[n][d] = k4;
        *(float4*)&vs[n][d] = v4;
    }
    __syncthreads();

    const float scale = __expf(fminf(logit_scale[h], 4.605170186f)); // ln(100)
    if (tid < 128) {
        int r = tid & 63;
        float* row = (tid < 64) ? qs[r] : ks[r];
        float ss = 0.0f;
#pragma unroll
        for (int d = 0; d < HDIM; d++) ss += row[d] * row[d];
        float rn = rsqrtf(ss);
        if (tid < 64) rn *= scale;
#pragma unroll
        for (int d = 0; d < HDIM; d++) row[d] *= rn;
    }
    __syncthreads();

    // ---- S = qn @ kn^T + bias + mask : 4x4 block per thread ----
    {
        const int i0 = (tid >> 4) * 4;
        const int j0 = (tid & 15) * 4;
        float acc[4][4];
#pragma unroll
        for (int a = 0; a < 4; a++)
#pragma unroll
            for (int b = 0; b < 4; b++) acc[a][b] = 0.0f;

#pragma unroll
        for (int d4 = 0; d4 < HDIM / 4; d4++) {
            float4 qv[4], kv[4];
#pragma unroll
            for (int a = 0; a < 4; a++) qv[a] = *(const float4*)&qs[i0 + a][d4 * 4];
#pragma unroll
            for (int b = 0; b < 4; b++) kv[b] = *(const float4*)&ks[j0 + b][d4 * 4];
#pragma unroll
            for (int a = 0; a < 4; a++)
#pragma unroll
                for (int b = 0; b < 4; b++) {
                    acc[a][b] = fmaf(qv[a].x, kv[b].x, acc[a][b]);
                    acc[a][b] = fmaf(qv[a].y, kv[b].y, acc[a][b]);
                    acc[a][b] = fmaf(qv[a].z, kv[b].z, acc[a][b]);
                    acc[a][b] = fmaf(qv[a].w, kv[b].w, acc[a][b]);
                }
        }

        const float* bh = bias + h * 4096;
        const float* mh = mask + (size_t)(w & (NUM_WIN - 1)) * 4096;
#pragma unroll
        for (int a = 0; a < 4; a++) {
            float4 bb = *(const float4*)&bh[(i0 + a) * 64 + j0];
            float4 mm = *(const float4*)&mh[(i0 + a) * 64 + j0];
            float4 o;
            o.x = acc[a][0] + bb.x + mm.x;
            o.y = acc[a][1] + bb.y + mm.y;
            o.z = acc[a][2] + bb.z + mm.z;
            o.w = acc[a][3] + bb.w + mm.w;
            *(float4*)&S[i0 + a][j0] = o;
        }
    }
    __syncthreads();

    // ---- softmax: 4 lanes per row ----
    {
        const int row = tid >> 2;
        const int q   = tid & 3;
        float* Sr = S[row];
        float mx = -1e30f;
#pragma unroll
        for (int j = 0; j < 16; j++) mx = fmaxf(mx, Sr[q * 16 + j]);
        mx = fmaxf(mx, __shfl_xor_sync(0xFFFFFFFF, mx, 1));
        mx = fmaxf(mx, __shfl_xor_sync(0xFFFFFFFF, mx, 2));
        float sum = 0.0f;
        float e[16];
#pragma unroll
        for (int j = 0; j < 16; j++) {
            e[j] = __expf(Sr[q * 16 + j] - mx);
            sum += e[j];
        }
        sum += __shfl_xor_sync(0xFFFFFFFF, sum, 1);
        sum += __shfl_xor_sync(0xFFFFFFFF, sum, 2);
        float inv = 1.0f / sum;
#pragma unroll
        for (int j = 0; j < 16; j++) Sr[q * 16 + j] = e[j] * inv;
    }
    __syncthreads();

    // ---- O = S @ V : 2 rows (r, r+32) x 4 cols per thread; V load shared ----
    {
        const int r  = tid >> 3;          // 0..31
        const int db = (tid & 7) * 4;     // 0,4,...,28
        float o0[4] = {0.0f, 0.0f, 0.0f, 0.0f};
        float o1[4] = {0.0f, 0.0f, 0.0f, 0.0f};
#pragma unroll
        for (int m = 0; m < NTOK; m++) {
            float4 v4 = *(const float4*)&vs[m][db];
            float s0 = S[r][m];
            float s1 = S[r + 32][m];
            o0[0] = fmaf(s0, v4.x, o0[0]); o0[1] = fmaf(s0, v4.y, o0[1]);
            o0[2] = fmaf(s0, v4.z, o0[2]); o0[3] = fmaf(s0, v4.w, o0[3]);
            o1[0] = fmaf(s1, v4.x, o1[0]); o1[1] = fmaf(s1, v4.y, o1[1]);
            o1[2] = fmaf(s1, v4.z, o1[2]); o1[3] = fmaf(s1, v4.w, o1[3]);
        }
        // tf32-round and store (proj GEMM expects valid tf32 operands)
        float4 w0, w1;
        w0.x = __uint_as_float(f2tf32(o0[0])); w0.y = __uint_as_float(f2tf32(o0[1]));
        w0.z = __uint_as_float(f2tf32(o0[2])); w0.w = __uint_as_float(f2tf32(o0[3]));
        w1.x = __uint_as_float(f2tf32(o1[0])); w1.y = __uint_as_float(f2tf32(o1[1]));
        w1.z = __uint_as_float(f2tf32(o1[2])); w1.w = __uint_as_float(f2tf32(o1[3]));
        *(float4*)(out + (size_t)(w * NTOK + r) * CDIM + h * HDIM + db)        = w0;
        *(float4*)(out + (size_t)(w * NTOK + r + 32) * CDIM + h * HDIM + db)   = w1;
    }
}

// ---------------- launch ----------------
extern "C" void kernel_launch(void* const* d_in, const int* in_sizes, int n_in,
                              void* d_out, int out_size)
{
    const float* x           = (const float*)d_in[0];
    const float* mask        = (const float*)d_in[1];
    const float* qkv_w       = (const float*)d_in[2];
    const float* q_bias      = (const float*)d_in[3];
    const float* v_bias      = (const float*)d_in[4];
    const float* logit_scale = (const float*)d_in[5];
    const float* cpb_w1      = (const float*)d_in[6];
    const float* cpb_b1      = (const float*)d_in[7];
    const float* cpb_w2      = (const float*)d_in[8];
    const float* proj_w      = (const float*)d_in[9];
    const float* proj_b      = (const float*)d_in[10];
    float* out = (float*)d_out;

    float *qkv_buf, *attn_buf, *xcvt_buf, *wqkv_buf, *wproj_buf, *bias_buf, *qb_buf;
    cudaGetSymbolAddress((void**)&qkv_buf, g_qkv);
    cudaGetSymbolAddress((void**)&attn_buf, g_attn);
    cudaGetSymbolAddress((void**)&xcvt_buf, g_xcvt);
    cudaGetSymbolAddress((void**)&wqkv_buf, g_wqkv);
    cudaGetSymbolAddress((void**)&wproj_buf, g_wproj);
    cudaGetSymbolAddress((void**)&bias_buf, g_bias);
    cudaGetSymbolAddress((void**)&qb_buf, g_qkvbias);

    cudaFuncSetAttribute(mma_gemm_bias,
                         cudaFuncAttributeMaxDynamicSharedMemorySize, GEMM_SMEM_BYTES);

    // launch order: QKV GEMM is the 4th launch (profiled)
    qkvbias_kernel<<<(QKV_N + 255) / 256, 256>>>(q_bias, v_bias, qb_buf);          // 1
    cpb_bias_kernel<<<NHEAD, 256>>>(cpb_w1, cpb_b1, cpb_w2, bias_buf);             // 2

    {   // 3: combined tf32 pre-rounding (x, qkv_w, proj_w)
        long long total4 = (long long)X4 + W1_4 + W2_4;
        int blocks = (int)((total4 + 255) / 256);
        cvt_all_kernel<<<blocks, 256>>>(x, qkv_w, proj_w, xcvt_buf, wqkv_buf, wproj_buf);
    }

    // 4: QKV projection [262144,512] @ [1536,512]^T
    {
        dim3 grid(QKV_N / BN, MTOT / BM);   // (6, 2048)
        mma_gemm_bias<<<grid, 512, GEMM_SMEM_BYTES>>>(xcvt_buf, wqkv_buf, qb_buf, qkv_buf,
                                                      MTOT, QKV_N, CDIM);
    }

    // 5: attention
    {
        dim3 grid(B_WIN, NHEAD);
        attn_kernel<<<grid, 256>>>(qkv_buf, mask, logit_scale, bias_buf, attn_buf);
    }

    // 6: output projection [262144,512] @ [512,512]^T -> d_out
    {
        dim3 grid(CDIM / BN, MTOT / BM);    // (2, 2048)
        mma_gemm_bias<<<grid, 512, GEMM_SMEM_BYTES>>>(attn_buf, wproj_buf, proj_b, out,
                                                      MTOT, CDIM, CDIM);
    }
}

// round 17
// speedup vs baseline: 1.1100x; 1.1100x over previous
#include <cuda_runtime.h>
#include <math.h>
#include <stdint.h>

// ---------------- problem constants ----------------
#define B_WIN   4096
#define NTOK    64
#define CDIM    512
#define NHEAD   16
#define HDIM    32
#define MTOT    (B_WIN * NTOK)      // 262144 rows
#define QKV_N   1536
#define NUM_WIN 256

// padded smem row strides (floats) — multiples of 4 for float4 access
#define QPAD 36     // 144 bytes
#define SSP  68     // 272 bytes

// ---------------- scratch (static device globals; no allocation) ----------------
__device__ float g_qkv[402653184];            // [MTOT, 1536]
__device__ float g_attn[134217728];           // [MTOT, 512]  (tf32-rounded attn out)
__device__ float g_xcvt[134217728];           // [MTOT, 512]  (tf32-rounded x)
__device__ float g_wqkv[QKV_N * CDIM];        // tf32-rounded qkv_w
__device__ float g_wproj[CDIM * CDIM];        // tf32-rounded proj_w
__device__ float g_bias[NHEAD * NTOK * NTOK]; // [16,64,64]
__device__ float g_qkvbias[QKV_N];

// ---------------- helpers ----------------
__device__ __forceinline__ uint32_t f2tf32(float f) {
    uint32_t u;
    asm("cvt.rna.tf32.f32 %0, %1;" : "=r"(u) : "f"(f));
    return u;
}

__device__ __forceinline__ void mma_tf32(float* c, const uint32_t* a, const uint32_t* b) {
    asm volatile(
        "mma.sync.aligned.m16n8k8.row.col.f32.tf32.tf32.f32 "
        "{%0,%1,%2,%3}, {%4,%5,%6,%7}, {%8,%9}, {%0,%1,%2,%3};"
        : "+f"(c[0]), "+f"(c[1]), "+f"(c[2]), "+f"(c[3])
        : "r"(a[0]), "r"(a[1]), "r"(a[2]), "r"(a[3]), "r"(b[0]), "r"(b[1]));
}

__device__ __forceinline__ void ldsm_x4(uint32_t* r, uint32_t saddr) {
    asm volatile("ldmatrix.sync.aligned.m8n8.x4.shared.b16 {%0,%1,%2,%3}, [%4];"
        : "=r"(r[0]), "=r"(r[1]), "=r"(r[2]), "=r"(r[3]) : "r"(saddr));
}

__device__ __forceinline__ void cp16(void* smem, const void* g) {
    uint32_t s = (uint32_t)__cvta_generic_to_shared(smem);
    asm volatile("cp.async.cg.shared.global [%0], [%1], 16;" :: "r"(s), "l"(g));
}

// ---------------- tiny setup kernels ----------------
__global__ void qkvbias_kernel(const float* __restrict__ q_bias,
                               const float* __restrict__ v_bias,
                               float* __restrict__ out) {
    int i = blockIdx.x * blockDim.x + threadIdx.x;
    if (i >= QKV_N) return;
    float v;
    if (i < 512)       v = q_bias[i];
    else if (i < 1024) v = 0.0f;
    else               v = v_bias[i - 1024];
    out[i] = v;
}

// combined tf32 rounding pass: x -> xcvt, qkv_w -> wqkv, proj_w -> wproj
#define X4   (MTOT * CDIM / 4)        // 33554432
#define W1_4 (QKV_N * CDIM / 4)       // 196608
#define W2_4 (CDIM * CDIM / 4)        // 65536
__global__ void cvt_all_kernel(const float* __restrict__ x,
                               const float* __restrict__ w1,
                               const float* __restrict__ w2,
                               float* __restrict__ xo,
                               float* __restrict__ w1o,
                               float* __restrict__ w2o) {
    long long i = (long long)blockIdx.x * blockDim.x + threadIdx.x;
    const float4* in;
    float4* out;
    long long idx;
    if (i < X4)                    { in = (const float4*)x;  out = (float4*)xo;  idx = i; }
    else if (i < X4 + W1_4)        { in = (const float4*)w1; out = (float4*)w1o; idx = i - X4; }
    else if (i < X4 + W1_4 + W2_4) { in = (const float4*)w2; out = (float4*)w2o; idx = i - X4 - W1_4; }
    else return;
    float4 v = in[idx];
    float4 o;
    o.x = __uint_as_float(f2tf32(v.x));
    o.y = __uint_as_float(f2tf32(v.y));
    o.z = __uint_as_float(f2tf32(v.z));
    o.w = __uint_as_float(f2tf32(v.w));
    out[idx] = o;
}

__device__ __forceinline__ float cpb_coord(int x) {
    float t = (float)x * (8.0f / 7.0f);
    float m = log2f(fabsf(t) + 1.0f) * (1.0f / 3.0f);
    return (t > 0.0f) ? m : ((t < 0.0f) ? -m : 0.0f);
}

__global__ void cpb_bias_kernel(const float* __restrict__ w1,
                                const float* __restrict__ b1,
                                const float* __restrict__ w2,
                                float* __restrict__ bias_out) {
    __shared__ float tableh[225];
    int h = blockIdx.x;
    int tid = threadIdx.x;
    for (int tt = tid; tt < 225; tt += blockDim.x) {
        int ih = tt / 15, iw = tt % 15;
        float t0 = cpb_coord(ih - 7);
        float t1 = cpb_coord(iw - 7);
        float val = 0.0f;
        for (int j = 0; j < 512; j++) {
            float hj = w1[2 * j] * t0 + w1[2 * j + 1] * t1 + b1[j];
            hj = fmaxf(hj, 0.0f);
            val += hj * w2[h * 512 + j];
        }
        tableh[tt] = 16.0f / (1.0f + expf(-val));
    }
    __syncthreads();
    for (int e = tid; e < NTOK * NTOK; e += blockDim.x) {
        int i = e >> 6, j = e & 63;
        int dh = (i >> 3) - (j >> 3) + 7;
        int dw = (i & 7) - (j & 7) + 7;
        bias_out[h * 4096 + e] = tableh[dh * 15 + dw];
    }
}

// ---------------- tf32 mma.sync GEMM: BK=16, 5-stage ring, ldmatrix ----------------
// (R12/R15-exact mainloop — measured best: tensor 56.5%)
#define BM 128
#define BN 128
#define BK 16
#define NSTAGE 5
#define SPAD 20                            // 16 floats + 4 pad
#define TSZ  (128 * SPAD)                  // 2560 floats per tile
#define STAGE_F (2 * TSZ)                  // A + B per stage (floats)
#define GEMM_SMEM_BYTES (NSTAGE * STAGE_F * 4)   // 102400

__global__ __launch_bounds__(256, 2)
void mma_gemm_bias(const float* __restrict__ A,
                   const float* __restrict__ B,
                   const float* __restrict__ bias,
                   float* __restrict__ C,
                   int M, int N, int K)
{
    extern __shared__ float sm[];
    const uint32_t sm_u32 = (uint32_t)__cvta_generic_to_shared(sm);

    const int tid  = threadIdx.x;
    const int wid  = tid >> 5;
    const int lane = tid & 31;
    const int g    = lane >> 2;
    const int t    = lane & 3;

    const int wm = (wid >> 2) * 64;
    const int wn = (wid & 3) * 32;

    const int bm = blockIdx.y * BM;
    const int bn = blockIdx.x * BN;

    const int lrow = tid >> 2;
    const int lc4  = (tid & 3) * 4;

    const float* Abase = A + (size_t)bm * K;
    const float* Bbase = B + (size_t)bn * K;

    const int arow = lane & 15;
    const int acol = (lane >> 4) * 4;
    const int brow = ((lane >> 4) << 3) + (lane & 7);
    const int bcol = ((lane >> 3) & 1) * 4;

    const uint32_t a_off = (uint32_t)(((wm + arow) * SPAD + acol) * 4);
    const uint32_t b_off = (uint32_t)(((wn + brow) * SPAD + bcol) * 4);

    float acc[4][4][4];
#pragma unroll
    for (int i = 0; i < 4; i++)
#pragma unroll
        for (int j = 0; j < 4; j++)
#pragma unroll
            for (int r = 0; r < 4; r++) acc[i][j][r] = 0.0f;

    const int NIT = K / BK;

    auto issue = [&](int s, int k0) {
        float* As = sm + s * STAGE_F;
        float* Bs = sm + s * STAGE_F + TSZ;
        cp16(&As[lrow * SPAD + lc4],        &Abase[(size_t)lrow * K + k0 + lc4]);
        cp16(&As[(lrow + 64) * SPAD + lc4], &Abase[(size_t)(lrow + 64) * K + k0 + lc4]);
        cp16(&Bs[lrow * SPAD + lc4],        &Bbase[(size_t)lrow * K + k0 + lc4]);
        cp16(&Bs[(lrow + 64) * SPAD + lc4], &Bbase[(size_t)(lrow + 64) * K + k0 + lc4]);
    };

    // prologue: fill NSTAGE-1 stages
#pragma unroll
    for (int s = 0; s < NSTAGE - 1; s++) {
        if (s < NIT) issue(s, s * BK);
        asm volatile("cp.async.commit_group;");
    }

    int slot = 0;                 // consume slot (mod NSTAGE)
    int fslot = NSTAGE - 1;       // fill slot

    for (int it = 0; it < NIT; it++) {
        asm volatile("cp.async.wait_group %0;" :: "n"(NSTAGE - 2));
        __syncthreads();

        {
            int nf = it + NSTAGE - 1;
            if (nf < NIT) issue(fslot, nf * BK);
            asm volatile("cp.async.commit_group;");
            if (++fslot == NSTAGE) fslot = 0;
        }

        const uint32_t st_base = sm_u32 + slot * (STAGE_F * 4);
        if (++slot == NSTAGE) slot = 0;
        const uint32_t a_base = st_base + a_off;
        const uint32_t b_base = st_base + (TSZ * 4) + b_off;

#pragma unroll
        for (int ks = 0; ks < BK; ks += 8) {
            uint32_t af[4][4];
#pragma unroll
            for (int mf = 0; mf < 4; mf++)
                ldsm_x4(af[mf], a_base + (uint32_t)((mf * 16 * SPAD + ks) * 4));

            uint32_t bf[2][4];
#pragma unroll
            for (int np = 0; np < 2; np++)
                ldsm_x4(bf[np], b_base + (uint32_t)((np * 16 * SPAD + ks) * 4));

#pragma unroll
            for (int mf = 0; mf < 4; mf++) {
#pragma unroll
                for (int np = 0; np < 2; np++) {
                    mma_tf32(acc[mf][2 * np],     af[mf], &bf[np][0]);
                    mma_tf32(acc[mf][2 * np + 1], af[mf], &bf[np][2]);
                }
            }
        }
    }

    // epilogue: add bias, store
#pragma unroll
    for (int mf = 0; mf < 4; mf++) {
#pragma unroll
        for (int nf = 0; nf < 4; nf++) {
            int row0 = bm + wm + mf * 16 + g;
            int col  = bn + wn + nf * 8 + 2 * t;
            float b0 = bias[col], b1 = bias[col + 1];
            float2 o0 = {acc[mf][nf][0] + b0, acc[mf][nf][1] + b1};
            float2 o1 = {acc[mf][nf][2] + b0, acc[mf][nf][3] + b1};
            *(float2*)&C[(size_t)row0 * N + col]       = o0;
            *(float2*)&C[(size_t)(row0 + 8) * N + col] = o1;
        }
    }
}

// ---------------- fused cosine attention per (head, window) ----------------
// grid(NHEAD, B_WIN): h fastest so the 16 heads of one window are adjacent
// in launch order -> each 6KB qkv row is read contiguously while hot in L2.
// 256 threads. Register-blocked S (4x4), O-phase 2-row blocking, warp softmax.
__global__ __launch_bounds__(256)
void attn_kernel(const float* __restrict__ qkv,
                 const float* __restrict__ mask,
                 const float* __restrict__ logit_scale,
                 const float* __restrict__ bias,
                 float* __restrict__ out)
{
    __shared__ float qs[NTOK][QPAD];
    __shared__ float ks[NTOK][QPAD];
    __shared__ float vs[NTOK][QPAD];
    __shared__ float S[NTOK][SSP];

    const int h = blockIdx.x;       // head (fastest)
    const int w = blockIdx.y;       // window
    const int tid = threadIdx.x;

    const float* base = qkv + (size_t)w * NTOK * QKV_N + h * HDIM;

    for (int idx = tid; idx < NTOK * HDIM / 4; idx += 256) {
        int n = idx >> 3;
        int d = (idx & 7) * 4;
        const float* r = base + n * QKV_N + d;
        float4 q4 = *(const float4*)(r);
        float4 k4 = *(const float4*)(r + 512);
        float4 v4 = *(const float4*)(r + 1024);
        *(float4*)&qs[n][d] = q4;
        *(float4*)&ks[n][d] = k4;
        *(float4*)&vs[n][d] = v4;
    }
    __syncthreads();

    const float scale = __expf(fminf(logit_scale[h], 4.605170186f)); // ln(100)
    if (tid < 128) {
        int r = tid & 63;
        float* row = (tid < 64) ? qs[r] : ks[r];
        float ss = 0.0f;
#pragma unroll
        for (int d = 0; d < HDIM; d++) ss += row[d] * row[d];
        float rn = rsqrtf(ss);
        if (tid < 64) rn *= scale;
#pragma unroll
        for (int d = 0; d < HDIM; d++) row[d] *= rn;
    }
    __syncthreads();

    // ---- S = qn @ kn^T + bias + mask : 4x4 block per thread ----
    {
        const int i0 = (tid >> 4) * 4;
        const int j0 = (tid & 15) * 4;
        float acc[4][4];
#pragma unroll
        for (int a = 0; a < 4; a++)
#pragma unroll
            for (int b = 0; b < 4; b++) acc[a][b] = 0.0f;

#pragma unroll
        for (int d4 = 0; d4 < HDIM / 4; d4++) {
            float4 qv[4], kv[4];
#pragma unroll
            for (int a = 0; a < 4; a++) qv[a] = *(const float4*)&qs[i0 + a][d4 * 4];
#pragma unroll
            for (int b = 0; b < 4; b++) kv[b] = *(const float4*)&ks[j0 + b][d4 * 4];
#pragma unroll
            for (int a = 0; a < 4; a++)
#pragma unroll
                for (int b = 0; b < 4; b++) {
                    acc[a][b] = fmaf(qv[a].x, kv[b].x, acc[a][b]);
                    acc[a][b] = fmaf(qv[a].y, kv[b].y, acc[a][b]);
                    acc[a][b] = fmaf(qv[a].z, kv[b].z, acc[a][b]);
                    acc[a][b] = fmaf(qv[a].w, kv[b].w, acc[a][b]);
                }
        }

        const float* bh = bias + h * 4096;
        const float* mh = mask + (size_t)(w & (NUM_WIN - 1)) * 4096;
#pragma unroll
        for (int a = 0; a < 4; a++) {
            float4 bb = *(const float4*)&bh[(i0 + a) * 64 + j0];
            float4 mm = *(const float4*)&mh[(i0 + a) * 64 + j0];
            float4 o;
            o.x = acc[a][0] + bb.x + mm.x;
            o.y = acc[a][1] + bb.y + mm.y;
            o.z = acc[a][2] + bb.z + mm.z;
            o.w = acc[a][3] + bb.w + mm.w;
            *(float4*)&S[i0 + a][j0] = o;
        }
    }
    __syncthreads();

    // ---- softmax: 4 lanes per row ----
    {
        const int row = tid >> 2;
        const int q   = tid & 3;
        float* Sr = S[row];
        float mx = -1e30f;
#pragma unroll
        for (int j = 0; j < 16; j++) mx = fmaxf(mx, Sr[q * 16 + j]);
        mx = fmaxf(mx, __shfl_xor_sync(0xFFFFFFFF, mx, 1));
        mx = fmaxf(mx, __shfl_xor_sync(0xFFFFFFFF, mx, 2));
        float sum = 0.0f;
        float e[16];
#pragma unroll
        for (int j = 0; j < 16; j++) {
            e[j] = __expf(Sr[q * 16 + j] - mx);
            sum += e[j];
        }
        sum += __shfl_xor_sync(0xFFFFFFFF, sum, 1);
        sum += __shfl_xor_sync(0xFFFFFFFF, sum, 2);
        float inv = 1.0f / sum;
#pragma unroll
        for (int j = 0; j < 16; j++) Sr[q * 16 + j] = e[j] * inv;
    }
    __syncthreads();

    // ---- O = S @ V : 2 rows (r, r+32) x 4 cols per thread; V load shared ----
    {
        const int r  = tid >> 3;          // 0..31
        const int db = (tid & 7) * 4;     // 0,4,...,28
        float o0[4] = {0.0f, 0.0f, 0.0f, 0.0f};
        float o1[4] = {0.0f, 0.0f, 0.0f, 0.0f};
#pragma unroll
        for (int m = 0; m < NTOK; m++) {
            float4 v4 = *(const float4*)&vs[m][db];
            float s0 = S[r][m];
            float s1 = S[r + 32][m];
            o0[0] = fmaf(s0, v4.x, o0[0]); o0[1] = fmaf(s0, v4.y, o0[1]);
            o0[2] = fmaf(s0, v4.z, o0[2]); o0[3] = fmaf(s0, v4.w, o0[3]);
            o1[0] = fmaf(s1, v4.x, o1[0]); o1[1] = fmaf(s1, v4.y, o1[1]);
            o1[2] = fmaf(s1, v4.z, o1[2]); o1[3] = fmaf(s1, v4.w, o1[3]);
        }
        // tf32-round and store (proj GEMM expects valid tf32 operands)
        float4 w0, w1;
        w0.x = __uint_as_float(f2tf32(o0[0])); w0.y = __uint_as_float(f2tf32(o0[1]));
        w0.z = __uint_as_float(f2tf32(o0[2])); w0.w = __uint_as_float(f2tf32(o0[3]));
        w1.x = __uint_as_float(f2tf32(o1[0])); w1.y = __uint_as_float(f2tf32(o1[1]));
        w1.z = __uint_as_float(f2tf32(o1[2])); w1.w = __uint_as_float(f2tf32(o1[3]));
        *(float4*)(out + (size_t)(w * NTOK + r) * CDIM + h * HDIM + db)        = w0;
        *(float4*)(out + (size_t)(w * NTOK + r + 32) * CDIM + h * HDIM + db)   = w1;
    }
}

// ---------------- launch ----------------
extern "C" void kernel_launch(void* const* d_in, const int* in_sizes, int n_in,
                              void* d_out, int out_size)
{
    const float* x           = (const float*)d_in[0];
    const float* mask        = (const float*)d_in[1];
    const float* qkv_w       = (const float*)d_in[2];
    const float* q_bias      = (const float*)d_in[3];
    const float* v_bias      = (const float*)d_in[4];
    const float* logit_scale = (const float*)d_in[5];
    const float* cpb_w1      = (const float*)d_in[6];
    const float* cpb_b1      = (const float*)d_in[7];
    const float* cpb_w2      = (const float*)d_in[8];
    const float* proj_w      = (const float*)d_in[9];
    const float* proj_b      = (const float*)d_in[10];
    float* out = (float*)d_out;

    float *qkv_buf, *attn_buf, *xcvt_buf, *wqkv_buf, *wproj_buf, *bias_buf, *qb_buf;
    cudaGetSymbolAddress((void**)&qkv_buf, g_qkv);
    cudaGetSymbolAddress((void**)&attn_buf, g_attn);
    cudaGetSymbolAddress((void**)&xcvt_buf, g_xcvt);
    cudaGetSymbolAddress((void**)&wqkv_buf, g_wqkv);
    cudaGetSymbolAddress((void**)&wproj_buf, g_wproj);
    cudaGetSymbolAddress((void**)&bias_buf, g_bias);
    cudaGetSymbolAddress((void**)&qb_buf, g_qkvbias);

    cudaFuncSetAttribute(mma_gemm_bias,
                         cudaFuncAttributeMaxDynamicSharedMemorySize, GEMM_SMEM_BYTES);

    // launch order: QKV GEMM is the 4th launch (profiled)
    qkvbias_kernel<<<(QKV_N + 255) / 256, 256>>>(q_bias, v_bias, qb_buf);          // 1
    cpb_bias_kernel<<<NHEAD, 256>>>(cpb_w1, cpb_b1, cpb_w2, bias_buf);             // 2

    {   // 3: combined tf32 pre-rounding (x, qkv_w, proj_w)
        long long total4 = (long long)X4 + W1_4 + W2_4;
        int blocks = (int)((total4 + 255) / 256);
        cvt_all_kernel<<<blocks, 256>>>(x, qkv_w, proj_w, xcvt_buf, wqkv_buf, wproj_buf);
    }

    // 4: QKV projection [262144,512] @ [1536,512]^T
    {
        dim3 grid(QKV_N / BN, MTOT / BM);   // (12, 2048)
        mma_gemm_bias<<<grid, 256, GEMM_SMEM_BYTES>>>(xcvt_buf, wqkv_buf, qb_buf, qkv_buf,
                                                      MTOT, QKV_N, CDIM);
    }

    // 5: attention — h fastest for L2 locality on qkv rows
    {
        dim3 grid(NHEAD, B_WIN);
        attn_kernel<<<grid, 256>>>(qkv_buf, mask, logit_scale, bias_buf, attn_buf);
    }

    // 6: output projection [262144,512] @ [512,512]^T -> d_out
    {
        dim3 grid(CDIM / BN, MTOT / BM);    // (4, 2048)
        mma_gemm_bias<<<grid, 256, GEMM_SMEM_BYTES>>>(attn_buf, wproj_buf, proj_b, out,
                                                      MTOT, CDIM, CDIM);
    }
}